// round 1
// baseline (speedup 1.0000x reference)
#include <cuda_runtime.h>
#include <cstdint>

#define B_  1024
#define F_  256
#define D_  64

// ---------------- scratch (device globals; no allocations allowed) ----------
__device__ float g_trans[2 * F_ * D_];   // [2,F,D]
__device__ float g_qkv  [3 * F_ * D_];   // [3,F,D]
__device__ float g_M    [F_ * F_];       // gate * cross
__device__ float g_s1   [B_ * F_];       // s[1,b,f]
__device__ float g_c    [B_ * F_];       // s[0,b,f] * s[2,b,f]

// ---------------- kernel A1: trans & qkv -------------------------------------
// trans[n,f,e] = sum_d indicator[f,d] * W_qk[n,d,e]   (n=0,1)
// qkv  [n,f,e] = sum_d indicator[f,d] * W_qkv[n,d,e]  (n=0,1,2)
__global__ void kA1(const float* __restrict__ ind,
                    const float* __restrict__ Wqk,
                    const float* __restrict__ Wqkv)
{
    __shared__ float sInd[D_];
    const int f = blockIdx.x;
    const int e = threadIdx.x;           // 64 threads
    sInd[e] = ind[f * D_ + e];
    __syncthreads();

    #pragma unroll
    for (int n = 0; n < 2; ++n) {
        float acc = 0.f;
        #pragma unroll 8
        for (int d = 0; d < D_; ++d)
            acc = fmaf(sInd[d], Wqk[n * D_ * D_ + d * D_ + e], acc);
        g_trans[n * F_ * D_ + f * D_ + e] = acc;
    }
    #pragma unroll
    for (int n = 0; n < 3; ++n) {
        float acc = 0.f;
        #pragma unroll 8
        for (int d = 0; d < D_; ++d)
            acc = fmaf(sInd[d], Wqkv[n * D_ * D_ + d * D_ + e], acc);
        g_qkv[n * F_ * D_ + f * D_ + e] = acc;
    }
}

// ---------------- kernel A2: M = (trans0_i . trans1_j > 0) ? qkv1_i.qkv0_j : 0
__global__ void kA2()
{
    __shared__ float sT0[D_];   // trans[0][i][:]
    __shared__ float sQ1[D_];   // qkv  [1][i][:]
    const int i = blockIdx.x;
    const int j = threadIdx.x;          // 256 threads
    if (j < 64)             sT0[j]      = g_trans[0 * F_ * D_ + i * D_ + j];
    else if (j < 128)       sQ1[j - 64] = g_qkv  [1 * F_ * D_ + i * D_ + (j - 64)];
    __syncthreads();

    float dg = 0.f, dc = 0.f;
    const float* __restrict__ t1 = &g_trans[1 * F_ * D_ + j * D_];
    const float* __restrict__ q0 = &g_qkv  [0 * F_ * D_ + j * D_];
    #pragma unroll 8
    for (int d = 0; d < D_; ++d) {
        dg = fmaf(sT0[d], t1[d], dg);
        dc = fmaf(sQ1[d], q0[d], dc);
    }
    g_M[i * F_ + j] = (dg > 0.f) ? dc : 0.f;
}

// ---------------- kernel B: s1 and c = s0*s2 (warp per (b,f)) ----------------
__global__ void kB(const float* __restrict__ feature)
{
    const int tid  = threadIdx.x;
    const int lane = tid & 31;
    const int gw   = blockIdx.x * 8 + (tid >> 5);   // global warp id = b*F + f
    const int b = gw >> 8;
    const int f = gw & 255;

    const float2 fv = *(const float2*)&feature[(size_t)(b * F_ + f) * D_ + (lane << 1)];
    float s[3];
    #pragma unroll
    for (int n = 0; n < 3; ++n) {
        const float2 qv = *(const float2*)&g_qkv[n * F_ * D_ + f * D_ + (lane << 1)];
        float p = fv.x * qv.x + fv.y * qv.y;
        #pragma unroll
        for (int off = 16; off > 0; off >>= 1)
            p += __shfl_xor_sync(0xffffffffu, p, off);
        s[n] = p;
    }
    if (lane == 0) {
        g_s1[b * F_ + f] = s[1];
        g_c [b * F_ + f] = s[0] * s[2];
    }
}

// ---------------- kernel C: out[b,i,d] = c[b,i] * sum_j M[i,j]*s1[b,j]*qkv2[j,d]
// block: 64 i-rows x (2 batches * 64 d) = 64x128 output tile, K = 256 in chunks of 32
// thread: 4 i x 8 cols, accumulators packed f32x2
__global__ void __launch_bounds__(256) kC(float* __restrict__ out)
{
    const int i0 = blockIdx.x * 64;      // 4 i-tiles
    const int b0 = blockIdx.y * 2;       // 512 batch pairs
    const int tid = threadIdx.x;
    const int cg = tid & 15;             // col group: 8 cols each (coalesced stores)
    const int ig = tid >> 4;             // i group: 4 rows each

    __shared__ float sMt[32][65];        // transposed M tile [kk][ii], pad -> conflict-free
    __shared__ float sQ [32][128];       // Q tile [kk][col], col = bb*64 + d
    __shared__ float sS1[2][F_];

    for (int t = tid; t < 512; t += 256)
        sS1[t >> 8][t & 255] = g_s1[(b0 + (t >> 8)) * F_ + (t & 255)];
    __syncthreads();

    const float* __restrict__ qkv2 = &g_qkv[2 * F_ * D_];

    unsigned long long acc[4][4];
    #pragma unroll
    for (int r = 0; r < 4; ++r)
        #pragma unroll
        for (int p = 0; p < 4; ++p) acc[r][p] = 0ull;

    for (int jt = 0; jt < F_; jt += 32) {
        // ---- load M tile (coalesced read, conflict-free transposed store)
        #pragma unroll
        for (int idx = tid; idx < 2048; idx += 256) {
            const int ii = idx >> 5, kk = idx & 31;
            sMt[kk][ii] = g_M[(i0 + ii) * F_ + jt + kk];
        }
        // ---- load Q tile: sQ[kk][bb*64+d] = qkv2[jt+kk][d] * s1[b0+bb][jt+kk]
        #pragma unroll
        for (int idx = tid; idx < 4096; idx += 256) {
            const int kk = idx >> 7, col = idx & 127;
            const int d = col & 63, bb = col >> 6;
            sQ[kk][col] = qkv2[(jt + kk) * D_ + d] * sS1[bb][jt + kk];
        }
        __syncthreads();

        #pragma unroll
        for (int kk = 0; kk < 32; ++kk) {
            // 8 contiguous Q floats = 4 natural f32x2 packs
            const ulonglong2 qa = *(const ulonglong2*)&sQ[kk][cg * 8];
            const ulonglong2 qb = *(const ulonglong2*)&sQ[kk][cg * 8 + 4];
            unsigned long long q[4] = {qa.x, qa.y, qb.x, qb.y};
            #pragma unroll
            for (int r = 0; r < 4; ++r) {
                const unsigned int mu = __float_as_uint(sMt[kk][ig * 4 + r]);
                unsigned long long m2;
                asm("mov.b64 %0, {%1, %1};" : "=l"(m2) : "r"(mu));
                #pragma unroll
                for (int p = 0; p < 4; ++p)
                    asm("fma.rn.f32x2 %0, %1, %2, %0;"
                        : "+l"(acc[r][p]) : "l"(m2), "l"(q[p]));
            }
        }
        __syncthreads();
    }

    // ---- epilogue: multiply by c[b,i], write out
    const int bb = cg >> 3;
    const int b  = b0 + bb;
    const int d0 = (cg & 7) * 8;
    #pragma unroll
    for (int r = 0; r < 4; ++r) {
        const int i = i0 + ig * 4 + r;
        const float cf = g_c[b * F_ + i];
        float o[8];
        #pragma unroll
        for (int p = 0; p < 4; ++p) {
            o[2 * p]     = __uint_as_float((unsigned)(acc[r][p] & 0xffffffffull)) * cf;
            o[2 * p + 1] = __uint_as_float((unsigned)(acc[r][p] >> 32)) * cf;
        }
        float4* dst = (float4*)&out[((size_t)b * F_ + i) * D_ + d0];
        dst[0] = make_float4(o[0], o[1], o[2], o[3]);
        dst[1] = make_float4(o[4], o[5], o[6], o[7]);
    }
}

// ---------------- launch ------------------------------------------------------
extern "C" void kernel_launch(void* const* d_in, const int* in_sizes, int n_in,
                              void* d_out, int out_size)
{
    const float* feature   = (const float*)d_in[0];
    const float* indicator = (const float*)d_in[1];
    const float* W_qk      = (const float*)d_in[2];
    const float* W_qkv     = (const float*)d_in[3];
    float* out = (float*)d_out;

    kA1<<<F_, D_>>>(indicator, W_qk, W_qkv);
    kA2<<<F_, F_>>>();
    kB<<<(B_ * F_) / 8, 256>>>(feature);
    kC<<<dim3(4, B_ / 2), 256>>>(out);
}

// round 3
// speedup vs baseline: 2.1873x; 2.1873x over previous
#include <cuda_runtime.h>
#include <cuda_bf16.h>
#include <cstdint>

#define B_  1024
#define F_  256
#define D_  64

// ---------------- scratch (device globals) -----------------------------------
__device__ float g_trans[2 * F_ * D_];
__device__ float g_qkv  [3 * F_ * D_];
__device__ float g_s1   [B_ * F_];
__device__ float g_c    [B_ * F_];
__device__ __nv_bfloat16 g_Mhi[F_ * F_];
__device__ __nv_bfloat16 g_Mlo[F_ * F_];

__device__ __forceinline__ uint32_t smem_u32(const void* p) {
    uint32_t a;
    asm("{ .reg .u64 t; cvta.to.shared.u64 t, %1; cvt.u32.u64 %0, t; }" : "=r"(a) : "l"(p));
    return a;
}

// ---------------- kernel A1: trans & qkv -------------------------------------
__global__ void kA1(const float* __restrict__ ind,
                    const float* __restrict__ Wqk,
                    const float* __restrict__ Wqkv)
{
    __shared__ float sInd[D_];
    const int f = blockIdx.x;
    const int e = threadIdx.x;
    sInd[e] = ind[f * D_ + e];
    __syncthreads();
    #pragma unroll
    for (int n = 0; n < 2; ++n) {
        float acc = 0.f;
        #pragma unroll 8
        for (int d = 0; d < D_; ++d) acc = fmaf(sInd[d], Wqk[n * D_ * D_ + d * D_ + e], acc);
        g_trans[n * F_ * D_ + f * D_ + e] = acc;
    }
    #pragma unroll
    for (int n = 0; n < 3; ++n) {
        float acc = 0.f;
        #pragma unroll 8
        for (int d = 0; d < D_; ++d) acc = fmaf(sInd[d], Wqkv[n * D_ * D_ + d * D_ + e], acc);
        g_qkv[n * F_ * D_ + f * D_ + e] = acc;
    }
}

// ------- kernel A2: M = gate*cross, split directly into bf16 hi/lo -----------
__global__ void kA2()
{
    __shared__ float sT0[D_];
    __shared__ float sQ1[D_];
    const int i = blockIdx.x;
    const int j = threadIdx.x;
    if (j < 64)       sT0[j]      = g_trans[i * D_ + j];
    else if (j < 128) sQ1[j - 64] = g_qkv[1 * F_ * D_ + i * D_ + (j - 64)];
    __syncthreads();
    const float4* __restrict__ t1 = (const float4*)&g_trans[F_ * D_ + j * D_];
    const float4* __restrict__ q0 = (const float4*)&g_qkv[j * D_];
    float dg = 0.f, dc = 0.f;
    #pragma unroll
    for (int d4 = 0; d4 < 16; ++d4) {
        const float4 a = t1[d4], b = q0[d4];
        dg += sT0[d4*4+0]*a.x + sT0[d4*4+1]*a.y + sT0[d4*4+2]*a.z + sT0[d4*4+3]*a.w;
        dc += sQ1[d4*4+0]*b.x + sQ1[d4*4+1]*b.y + sQ1[d4*4+2]*b.z + sQ1[d4*4+3]*b.w;
    }
    const float m = (dg > 0.f) ? dc : 0.f;
    const __nv_bfloat16 h = __float2bfloat16(m);
    g_Mhi[i * F_ + j] = h;
    g_Mlo[i * F_ + j] = __float2bfloat16(m - __bfloat162float(h));
}

// ---------------- kernel B: s1 and c = s0*s2 (4 rows/warp) -------------------
__global__ void kB(const float* __restrict__ feature)
{
    const int tid = threadIdx.x;
    const int lane = tid & 31;
    const int warpg = blockIdx.x * 8 + (tid >> 5);
    const int row = warpg * 4 + (lane >> 3);   // global (b,f) row
    const int seg = lane & 7;
    const int f = row & 255;

    const float4* fp = (const float4*)&feature[(size_t)row * D_ + seg * 8];
    const float4 f0 = fp[0], f1 = fp[1];
    float p[3];
    #pragma unroll
    for (int n = 0; n < 3; ++n) {
        const float4* qp = (const float4*)&g_qkv[n * F_ * D_ + f * D_ + seg * 8];
        const float4 q0 = qp[0], q1 = qp[1];
        float a = f0.x * q0.x + f0.y * q0.y + f0.z * q0.z + f0.w * q0.w
                + f1.x * q1.x + f1.y * q1.y + f1.z * q1.z + f1.w * q1.w;
        a += __shfl_xor_sync(0xffffffffu, a, 1);
        a += __shfl_xor_sync(0xffffffffu, a, 2);
        a += __shfl_xor_sync(0xffffffffu, a, 4);
        p[n] = a;
    }
    if (seg == 0) {
        g_s1[row] = p[1];
        g_c [row] = p[0] * p[2];
    }
}

// ---------------- kernel C: legacy HMMA GEMM (bf16 split-3) ------------------
// out[b,i,d] = c[b,i] * sum_j M[i,j] * s1[b,j] * V[j,d]
// CTA: 128 i-rows x 128 cols (2 batches x 64 d), K=256 in 4 chunks of 64.
// smem: sS1[512]f32 | sA[2][128][64]bf16 (hi,lo) | sB[2][128][64]bf16 (hi,lo)
#define SMC_S1   0u
#define SMC_A    2048u
#define SMC_B    34816u
#define SMC_TOT  67584u

__global__ void __launch_bounds__(256, 2) kC(float* __restrict__ out)
{
    extern __shared__ char smem[];
    const uint32_t sb = smem_u32(smem);
    const int tid = threadIdx.x, lane = tid & 31, wid = tid >> 5;
    const int i0 = blockIdx.x * 128;
    const int b0 = blockIdx.y * 2;
    const int wm = wid & 3;          // m warp: 4 x 32 rows
    const int wn = wid >> 2;         // n warp: 2 x 64 cols (one batch each)

    float* sS1 = (float*)smem;
    for (int t = tid; t < 512; t += 256)
        sS1[t] = g_s1[(b0 + (t >> 8)) * F_ + (t & 255)];

    // ldmatrix per-lane address bases (SW: 16B segment ^= (row&7))
    const int lrow = lane & 15;
    const uint32_t lkb = (lane >> 4) * 16;     // byte offset of lane's k-half
    uint32_t aBase[2], aX[2], bBase[4], bX[4];
    #pragma unroll
    for (int g = 0; g < 2; ++g) {
        const int r = wm * 32 + g * 16 + lrow;
        aBase[g] = sb + SMC_A + r * 128;
        aX[g] = (uint32_t)((r & 7) << 4);
    }
    #pragma unroll
    for (int g = 0; g < 4; ++g) {
        const int r = wn * 64 + g * 16 + lrow;
        bBase[g] = sb + SMC_B + r * 128;
        bX[g] = (uint32_t)((r & 7) << 4);
    }

    // B build constants: col fixed per thread, k-pair varies
    const int bcol = tid & 127;
    const int bd = bcol & 63;
    const float* sS1b = sS1 + ((bcol >> 6) << 8);
    const uint32_t bstore = sb + SMC_B + (uint32_t)bcol * 128;
    const uint32_t bx = (uint32_t)((bcol & 7) << 4);

    const float* __restrict__ Vt = &g_qkv[2 * F_ * D_];

    float acc[2][8][4];
    #pragma unroll
    for (int m = 0; m < 2; ++m)
        #pragma unroll
        for (int f = 0; f < 8; ++f)
            #pragma unroll
            for (int q = 0; q < 4; ++q) acc[m][f][q] = 0.f;

    __syncthreads();   // sS1 ready

    for (int c = 0; c < 4; ++c) {
        // ---- A chunk: copy 128x64 bf16 hi & lo, 16B-vectorized, swizzled
        #pragma unroll
        for (int sp = 0; sp < 2; ++sp) {
            const uint4* __restrict__ src = (const uint4*)(sp ? g_Mlo : g_Mhi);
            #pragma unroll
            for (int it = 0; it < 4; ++it) {
                const int pid = tid + it * 256;          // 0..1023
                const int r = pid >> 3, ks = pid & 7;
                const uint4 v = src[((i0 + r) * 256 + c * 64 + ks * 8) >> 3];
                const uint32_t ad = sb + SMC_A + (uint32_t)sp * 16384u + (uint32_t)r * 128u
                                  + (uint32_t)((ks * 16) ^ ((r & 7) << 4));
                asm volatile("st.shared.v4.b32 [%0], {%1,%2,%3,%4};"
                             :: "r"(ad), "r"(v.x), "r"(v.y), "r"(v.z), "r"(v.w));
            }
        }
        // ---- B chunk: H[col][k] = s1[b,j]*V[j,d], j = c*64+k, hi/lo bf16
        #pragma unroll
        for (int it = 0; it < 16; ++it) {
            const int kp = (tid >> 7) + it * 2;          // k-pair 0..31
            const int j = c * 64 + kp * 2;
            const float H0 = sS1b[j]     * __ldg(&Vt[j * 64 + bd]);
            const float H1 = sS1b[j + 1] * __ldg(&Vt[(j + 1) * 64 + bd]);
            const float h0 = __bfloat162float(__float2bfloat16(H0));
            const float h1 = __bfloat162float(__float2bfloat16(H1));
            uint32_t uhi, ulo;
            asm("cvt.rn.bf16x2.f32 %0, %1, %2;" : "=r"(uhi) : "f"(h1), "f"(h0));
            asm("cvt.rn.bf16x2.f32 %0, %1, %2;" : "=r"(ulo) : "f"(H1 - h1), "f"(H0 - h0));
            const uint32_t ad = bstore + (uint32_t)((kp * 4) ^ (int)bx);
            asm volatile("st.shared.b32 [%0], %1;" :: "r"(ad), "r"(uhi));
            asm volatile("st.shared.b32 [%0], %1;" :: "r"(ad + 16384u), "r"(ulo));
        }
        __syncthreads();

        // ---- MMA: 3 splits x 4 k16 steps
        #pragma unroll
        for (int sp = 0; sp < 3; ++sp) {
            const uint32_t ao = (sp == 2) ? 16384u : 0u;
            const uint32_t bo = (sp == 1) ? 16384u : 0u;
            #pragma unroll
            for (int k16 = 0; k16 < 4; ++k16) {
                const uint32_t kb = (uint32_t)(k16 * 32);
                uint32_t a[2][4];
                #pragma unroll
                for (int g = 0; g < 2; ++g) {
                    const uint32_t ad = aBase[g] + ao + ((kb + lkb) ^ aX[g]);
                    asm volatile("ldmatrix.sync.aligned.m8n8.x4.shared.b16 {%0,%1,%2,%3}, [%4];"
                                 : "=r"(a[g][0]), "=r"(a[g][1]), "=r"(a[g][2]), "=r"(a[g][3])
                                 : "r"(ad));
                }
                #pragma unroll
                for (int g = 0; g < 4; ++g) {
                    uint32_t b0r, b1r, b2r, b3r;
                    const uint32_t ad = bBase[g] + bo + ((kb + lkb) ^ bX[g]);
                    asm volatile("ldmatrix.sync.aligned.m8n8.x4.shared.b16 {%0,%1,%2,%3}, [%4];"
                                 : "=r"(b0r), "=r"(b1r), "=r"(b2r), "=r"(b3r)
                                 : "r"(ad));
                    #pragma unroll
                    for (int m = 0; m < 2; ++m) {
                        asm volatile(
                            "mma.sync.aligned.m16n8k16.row.col.f32.bf16.bf16.f32 "
                            "{%0,%1,%2,%3}, {%4,%5,%6,%7}, {%8,%9}, {%0,%1,%2,%3};"
                            : "+f"(acc[m][2*g][0]), "+f"(acc[m][2*g][1]),
                              "+f"(acc[m][2*g][2]), "+f"(acc[m][2*g][3])
                            : "r"(a[m][0]), "r"(a[m][1]), "r"(a[m][2]), "r"(a[m][3]),
                              "r"(b0r), "r"(b2r));
                        asm volatile(
                            "mma.sync.aligned.m16n8k16.row.col.f32.bf16.bf16.f32 "
                            "{%0,%1,%2,%3}, {%4,%5,%6,%7}, {%8,%9}, {%0,%1,%2,%3};"
                            : "+f"(acc[m][2*g+1][0]), "+f"(acc[m][2*g+1][1]),
                              "+f"(acc[m][2*g+1][2]), "+f"(acc[m][2*g+1][3])
                            : "r"(a[m][0]), "r"(a[m][1]), "r"(a[m][2]), "r"(a[m][3]),
                              "r"(b1r), "r"(b3r));
                    }
                }
            }
        }
        __syncthreads();
    }

    // ---- epilogue: scale by c[b,i] and store float2 per frag-row
    const int b = b0 + wn;
    const int iBase = i0 + wm * 32 + (lane >> 2);
    const int dBase = (lane & 3) * 2;
    #pragma unroll
    for (int m = 0; m < 2; ++m) {
        const int i_0 = iBase + m * 16;
        const float cf0 = g_c[b * F_ + i_0];
        const float cf1 = g_c[b * F_ + i_0 + 8];
        float2* dst0 = (float2*)&out[((size_t)b * F_ + i_0) * D_];
        float2* dst1 = (float2*)&out[((size_t)b * F_ + i_0 + 8) * D_];
        #pragma unroll
        for (int g = 0; g < 4; ++g)
            #pragma unroll
            for (int h = 0; h < 2; ++h) {
                const int d = g * 16 + h * 8 + dBase;
                const float* A4 = acc[m][2*g + h];
                dst0[d >> 1] = make_float2(A4[0] * cf0, A4[1] * cf0);
                dst1[d >> 1] = make_float2(A4[2] * cf1, A4[3] * cf1);
            }
    }
}

// ---------------- launch ------------------------------------------------------
extern "C" void kernel_launch(void* const* d_in, const int* in_sizes, int n_in,
                              void* d_out, int out_size)
{
    const float* feature   = (const float*)d_in[0];
    const float* indicator = (const float*)d_in[1];
    const float* W_qk      = (const float*)d_in[2];
    const float* W_qkv     = (const float*)d_in[3];
    float* out = (float*)d_out;

    cudaFuncSetAttribute(kC, cudaFuncAttributeMaxDynamicSharedMemorySize, SMC_TOT);

    kA1<<<F_, D_>>>(indicator, W_qk, W_qkv);
    kA2<<<F_, F_>>>();
    kB<<<(B_ * F_) / 32, 256>>>(feature);
    kC<<<dim3(2, 512), 256, SMC_TOT>>>(out);
}

// round 4
// speedup vs baseline: 2.5111x; 1.1480x over previous
#include <cuda_runtime.h>
#include <cuda_bf16.h>
#include <cstdint>

#define B_  1024
#define F_  256
#define D_  64

// ---------------- scratch (device globals) -----------------------------------
__device__ float g_trans[2 * F_ * D_];
__device__ float g_qkv  [3 * F_ * D_];
__device__ float g_s1   [B_ * F_];
__device__ float g_c    [B_ * F_];
__device__ __nv_bfloat16 g_Mhi[F_ * F_];
__device__ __nv_bfloat16 g_Mlo[F_ * F_];

__device__ __forceinline__ uint32_t smem_u32(const void* p) {
    uint32_t a;
    asm("{ .reg .u64 t; cvta.to.shared.u64 t, %1; cvt.u32.u64 %0, t; }" : "=r"(a) : "l"(p));
    return a;
}

// ---------------- kernel A1: trans & qkv (4 f-rows per block) ----------------
__global__ void kA1(const float* __restrict__ ind,
                    const float* __restrict__ Wqk,
                    const float* __restrict__ Wqkv)
{
    __shared__ float sInd[4][D_];
    const int fg = threadIdx.x >> 6;
    const int e  = threadIdx.x & 63;
    const int f  = blockIdx.x * 4 + fg;
    sInd[fg][e] = ind[f * D_ + e];
    __syncthreads();
    const float* si = sInd[fg];
    #pragma unroll
    for (int n = 0; n < 2; ++n) {
        float acc = 0.f;
        #pragma unroll 8
        for (int d = 0; d < D_; ++d) acc = fmaf(si[d], Wqk[n * D_ * D_ + d * D_ + e], acc);
        g_trans[n * F_ * D_ + f * D_ + e] = acc;
    }
    #pragma unroll
    for (int n = 0; n < 3; ++n) {
        float acc = 0.f;
        #pragma unroll 8
        for (int d = 0; d < D_; ++d) acc = fmaf(si[d], Wqkv[n * D_ * D_ + d * D_ + e], acc);
        g_qkv[n * F_ * D_ + f * D_ + e] = acc;
    }
}

// ------ kernel AB (fused): blocks 0..255 = M build; blocks 256.. = s pass ----
__global__ void kAB(const float* __restrict__ feature)
{
    if (blockIdx.x < 256) {
        // ---- kA2: M[i,j] = (trans0_i.trans1_j > 0) ? qkv1_i.qkv0_j : 0 -> hi/lo
        __shared__ float sT0[D_];
        __shared__ float sQ1[D_];
        const int i = blockIdx.x;
        const int j = threadIdx.x;
        if (j < 64)       sT0[j]      = g_trans[i * D_ + j];
        else if (j < 128) sQ1[j - 64] = g_qkv[1 * F_ * D_ + i * D_ + (j - 64)];
        __syncthreads();
        const float4* __restrict__ t1 = (const float4*)&g_trans[F_ * D_ + j * D_];
        const float4* __restrict__ q0 = (const float4*)&g_qkv[j * D_];
        float dg = 0.f, dc = 0.f;
        #pragma unroll
        for (int d4 = 0; d4 < 16; ++d4) {
            const float4 a = t1[d4], b = q0[d4];
            dg += sT0[d4*4+0]*a.x + sT0[d4*4+1]*a.y + sT0[d4*4+2]*a.z + sT0[d4*4+3]*a.w;
            dc += sQ1[d4*4+0]*b.x + sQ1[d4*4+1]*b.y + sQ1[d4*4+2]*b.z + sQ1[d4*4+3]*b.w;
        }
        const float m = (dg > 0.f) ? dc : 0.f;
        const __nv_bfloat16 h = __float2bfloat16(m);
        g_Mhi[i * F_ + j] = h;
        g_Mlo[i * F_ + j] = __float2bfloat16(m - __bfloat162float(h));
    } else {
        // ---- kB: s1 and c = s0*s2
        const int tid = threadIdx.x;
        const int lane = tid & 31;
        const int warpg = (blockIdx.x - 256) * 8 + (tid >> 5);
        const int row = warpg * 4 + (lane >> 3);
        const int seg = lane & 7;
        const int f = row & 255;
        const float4* fp = (const float4*)&feature[(size_t)row * D_ + seg * 8];
        const float4 f0 = fp[0], f1 = fp[1];
        float p[3];
        #pragma unroll
        for (int n = 0; n < 3; ++n) {
            const float4* qp = (const float4*)&g_qkv[n * F_ * D_ + f * D_ + seg * 8];
            const float4 q0 = qp[0], q1 = qp[1];
            float a = f0.x * q0.x + f0.y * q0.y + f0.z * q0.z + f0.w * q0.w
                    + f1.x * q1.x + f1.y * q1.y + f1.z * q1.z + f1.w * q1.w;
            a += __shfl_xor_sync(0xffffffffu, a, 1);
            a += __shfl_xor_sync(0xffffffffu, a, 2);
            a += __shfl_xor_sync(0xffffffffu, a, 4);
            p[n] = a;
        }
        if (seg == 0) {
            g_s1[row] = p[1];
            g_c [row] = p[0] * p[2];
        }
    }
}

// ---------------- kernel C: persistent HMMA GEMM -----------------------------
// unit u: i-half h = u>>9, batch-pair bp = u&511; tile 128 rows x 128 cols.
// smem: s1[512]f32 | A[2sp][128r][256k] (128 KB, per-h) | B[2buf][2sp][128c][64k]
#define SMS1  0u
#define SMA   2048u
#define SMB   133120u
#define SMTOT 198656u

__global__ void __launch_bounds__(256, 1) kC(float* __restrict__ out)
{
    extern __shared__ char smem[];
    const uint32_t sb = smem_u32(smem);
    const int tid = threadIdx.x, lane = tid & 31, wid = tid >> 5;
    const int wm = wid & 3;          // 4 x 32 rows
    const int wn = wid >> 2;         // 2 x 64 cols (one batch each)

    // ldmatrix bases
    uint32_t aad[2]; int ax[2];
    #pragma unroll
    for (int m = 0; m < 2; ++m) {
        const int r = wm * 32 + m * 16 + (lane & 15);
        aad[m] = sb + SMA + (uint32_t)r * 512u;
        ax[m] = r & 7;
    }
    uint32_t bad[4]; int bxg[4];
    #pragma unroll
    for (int g = 0; g < 4; ++g) {
        const int r = wn * 64 + g * 16 + (lane & 15);
        bad[g] = sb + SMB + (uint32_t)r * 128u;
        bxg[g] = r & 7;
    }
    const int lk = lane >> 4;        // k-half selector for ldmatrix

    // B build mapping: col = tid/2, k-half = tid&1  (2-way STS conflicts only)
    const int bcol = tid >> 1, kh = tid & 1;
    const int bd = bcol & 63, bbl = bcol >> 6;
    const uint32_t bst = sb + SMB + (uint32_t)bcol * 128u;
    const int bxc = bcol & 7;

    float* s1s = (float*)smem;
    const float* __restrict__ Vt = &g_qkv[2 * F_ * D_];

    int curh = -1;
    for (int u = blockIdx.x; u < 1024; u += 152) {
        const int h = u >> 9, bp = u & 511;
        const int i0 = h * 128, b0 = bp * 2;

        __syncthreads();                      // prior unit's MMA/epilogue done
        if (h != curh) {
            curh = h;
            #pragma unroll
            for (int sp = 0; sp < 2; ++sp) {
                const uint4* __restrict__ src = (const uint4*)(sp ? g_Mlo : g_Mhi);
                #pragma unroll
                for (int it = 0; it < 16; ++it) {
                    const int idx = tid + it * 256;       // 0..4095
                    const int r = idx >> 5, seg = idx & 31;
                    const uint4 v = src[(i0 + r) * 32 + seg];
                    const uint32_t ad = sb + SMA + (uint32_t)sp * 65536u
                                      + (uint32_t)r * 512u + (uint32_t)((seg ^ (r & 7)) << 4);
                    asm volatile("st.shared.v4.b32 [%0], {%1,%2,%3,%4};"
                                 :: "r"(ad), "r"(v.x), "r"(v.y), "r"(v.z), "r"(v.w));
                }
            }
        }
        for (int t = tid; t < 512; t += 256)
            s1s[t] = g_s1[(b0 + (t >> 8)) * F_ + (t & 255)];
        __syncthreads();                      // fills visible

        float acc[2][8][4];
        #pragma unroll
        for (int m = 0; m < 2; ++m)
            #pragma unroll
            for (int f = 0; f < 8; ++f)
                #pragma unroll
                for (int q = 0; q < 4; ++q) acc[m][f][q] = 0.f;

        for (int c = 0; c < 4; ++c) {
            const uint32_t bufo = (uint32_t)(c & 1) * 32768u;
            // ---- build B[c]: H[col][k] = s1[b,j]*V[j,d], j = c*64 + kh*32 + k
            {
                const float* s1r = s1s + bbl * 256 + c * 64 + kh * 32;
                const float* vr  = Vt + (c * 64 + kh * 32) * 64 + bd;
                #pragma unroll
                for (int kp = 0; kp < 16; ++kp) {
                    const float H0 = s1r[2 * kp]     * vr[(2 * kp) * 64];
                    const float H1 = s1r[2 * kp + 1] * vr[(2 * kp + 1) * 64];
                    uint32_t uhi;
                    asm("cvt.rn.bf16x2.f32 %0, %1, %2;" : "=r"(uhi) : "f"(H1), "f"(H0));
                    const float hf0 = __uint_as_float(uhi << 16);
                    const float hf1 = __uint_as_float(uhi & 0xffff0000u);
                    uint32_t ulo;
                    asm("cvt.rn.bf16x2.f32 %0, %1, %2;" : "=r"(ulo) : "f"(H1 - hf1), "f"(H0 - hf0));
                    const int bseg = kh * 4 + (kp >> 2);
                    const uint32_t ad = bst + bufo + (uint32_t)((bseg ^ bxc) << 4)
                                      + (uint32_t)((kp * 4) & 12);
                    asm volatile("st.shared.b32 [%0], %1;" :: "r"(ad), "r"(uhi));
                    asm volatile("st.shared.b32 [%0], %1;" :: "r"(ad + 16384u), "r"(ulo));
                }
            }
            __syncthreads();                  // B[c] ready (prior reader of this buf done)

            // ---- MMA chunk c: A-hi reused for 2 splits, B-hi reused for 2
            #pragma unroll
            for (int k16 = 0; k16 < 4; ++k16) {
                uint32_t ah[2][4], al[2][4];
                #pragma unroll
                for (int m = 0; m < 2; ++m) {
                    const int seg = c * 8 + k16 * 2 + lk;
                    const uint32_t adh = aad[m] + (uint32_t)((seg ^ ax[m]) << 4);
                    asm volatile("ldmatrix.sync.aligned.m8n8.x4.shared.b16 {%0,%1,%2,%3}, [%4];"
                                 : "=r"(ah[m][0]), "=r"(ah[m][1]), "=r"(ah[m][2]), "=r"(ah[m][3])
                                 : "r"(adh));
                    asm volatile("ldmatrix.sync.aligned.m8n8.x4.shared.b16 {%0,%1,%2,%3}, [%4];"
                                 : "=r"(al[m][0]), "=r"(al[m][1]), "=r"(al[m][2]), "=r"(al[m][3])
                                 : "r"(adh + 65536u));
                }
                #pragma unroll
                for (int g = 0; g < 4; ++g) {
                    const int seg = k16 * 2 + lk;
                    const uint32_t adb = bad[g] + bufo + (uint32_t)((seg ^ bxg[g]) << 4);
                    uint32_t hb[4], lb[4];
                    asm volatile("ldmatrix.sync.aligned.m8n8.x4.shared.b16 {%0,%1,%2,%3}, [%4];"
                                 : "=r"(hb[0]), "=r"(hb[1]), "=r"(hb[2]), "=r"(hb[3]) : "r"(adb));
                    asm volatile("ldmatrix.sync.aligned.m8n8.x4.shared.b16 {%0,%1,%2,%3}, [%4];"
                                 : "=r"(lb[0]), "=r"(lb[1]), "=r"(lb[2]), "=r"(lb[3]) : "r"(adb + 16384u));
                    #pragma unroll
                    for (int m = 0; m < 2; ++m) {
#define MMA_(ACC, A0,A1,A2,A3, B0,B1) \
    asm volatile("mma.sync.aligned.m16n8k16.row.col.f32.bf16.bf16.f32 " \
        "{%0,%1,%2,%3}, {%4,%5,%6,%7}, {%8,%9}, {%0,%1,%2,%3};" \
        : "+f"(ACC[0]), "+f"(ACC[1]), "+f"(ACC[2]), "+f"(ACC[3]) \
        : "r"(A0), "r"(A1), "r"(A2), "r"(A3), "r"(B0), "r"(B1))
                        MMA_(acc[m][2*g],   ah[m][0],ah[m][1],ah[m][2],ah[m][3], hb[0],hb[2]);
                        MMA_(acc[m][2*g+1], ah[m][0],ah[m][1],ah[m][2],ah[m][3], hb[1],hb[3]);
                        MMA_(acc[m][2*g],   ah[m][0],ah[m][1],ah[m][2],ah[m][3], lb[0],lb[2]);
                        MMA_(acc[m][2*g+1], ah[m][0],ah[m][1],ah[m][2],ah[m][3], lb[1],lb[3]);
                        MMA_(acc[m][2*g],   al[m][0],al[m][1],al[m][2],al[m][3], hb[0],hb[2]);
                        MMA_(acc[m][2*g+1], al[m][0],al[m][1],al[m][2],al[m][3], hb[1],hb[3]);
#undef MMA_
                    }
                }
            }
        }

        // ---- epilogue: scale by c[b,i], store
        const int b = b0 + wn;
        #pragma unroll
        for (int m = 0; m < 2; ++m) {
            const int i = i0 + wm * 32 + m * 16 + (lane >> 2);
            const float cf0 = g_c[b * F_ + i];
            const float cf1 = g_c[b * F_ + i + 8];
            float2* d0 = (float2*)&out[((size_t)b * F_ + i) * D_];
            float2* d1 = (float2*)&out[((size_t)b * F_ + i + 8) * D_];
            #pragma unroll
            for (int g = 0; g < 4; ++g)
                #pragma unroll
                for (int hh = 0; hh < 2; ++hh) {
                    const int d = g * 16 + hh * 8 + (lane & 3) * 2;
                    const float* A4 = acc[m][2*g + hh];
                    d0[d >> 1] = make_float2(A4[0] * cf0, A4[1] * cf0);
                    d1[d >> 1] = make_float2(A4[2] * cf1, A4[3] * cf1);
                }
        }
    }
}

// ---------------- launch ------------------------------------------------------
extern "C" void kernel_launch(void* const* d_in, const int* in_sizes, int n_in,
                              void* d_out, int out_size)
{
    const float* feature   = (const float*)d_in[0];
    const float* indicator = (const float*)d_in[1];
    const float* W_qk      = (const float*)d_in[2];
    const float* W_qkv     = (const float*)d_in[3];
    float* out = (float*)d_out;

    cudaFuncSetAttribute(kC, cudaFuncAttributeMaxDynamicSharedMemorySize, SMTOT);

    kA1<<<F_ / 4, 256>>>(indicator, W_qk, W_qkv);
    kAB<<<256 + (B_ * F_) / 32, 256>>>(feature);
    kC<<<152, 256, SMTOT>>>(out);
}

// round 5
// speedup vs baseline: 2.9241x; 1.1645x over previous
#include <cuda_runtime.h>
#include <cuda_bf16.h>
#include <cstdint>

#define B_  1024
#define F_  256
#define D_  64

// ---------------- scratch (device globals) -----------------------------------
__device__ float g_trans[2 * F_ * D_];
__device__ float g_qkv  [3 * F_ * D_];
__device__ float g_s1   [B_ * F_];
__device__ float g_c    [B_ * F_];
__device__ float g_vt   [D_ * F_];          // Vt transposed: [d][j]
__device__ __nv_bfloat16 g_Mhi[F_ * F_];
__device__ __nv_bfloat16 g_Mlo[F_ * F_];

__device__ __forceinline__ uint32_t smem_u32(const void* p) {
    uint32_t a;
    asm("{ .reg .u64 t; cvta.to.shared.u64 t, %1; cvt.u32.u64 %0, t; }" : "=r"(a) : "l"(p));
    return a;
}

// ---------------- kernel A1: one output element per thread -------------------
// grid 256 (f), block 320: n = tid/64 (0..4), e = tid%64
__global__ void kA1(const float* __restrict__ ind,
                    const float* __restrict__ Wqk,
                    const float* __restrict__ Wqkv)
{
    __shared__ float sInd[D_];
    const int f = blockIdx.x, t = threadIdx.x;
    const int n = t >> 6, e = t & 63;
    if (t < 64) sInd[t] = ind[f * D_ + t];
    __syncthreads();
    const float* __restrict__ W = (n < 2) ? (Wqk + n * D_ * D_) : (Wqkv + (n - 2) * D_ * D_);
    float acc = 0.f;
    #pragma unroll 16
    for (int d = 0; d < D_; ++d) acc = fmaf(sInd[d], W[d * D_ + e], acc);
    if (n < 2) g_trans[n * F_ * D_ + f * D_ + e] = acc;
    else       g_qkv[(n - 2) * F_ * D_ + f * D_ + e] = acc;
}

// ------ kernel AB (fused): [0,256) M build; [256,320) Vt transpose; rest s ---
__global__ void kAB(const float* __restrict__ feature)
{
    const int bi = blockIdx.x;
    if (bi < 256) {
        __shared__ float sT0[D_];
        __shared__ float sQ1[D_];
        const int i = bi;
        const int j = threadIdx.x;
        if (j < 64)       sT0[j]      = g_trans[i * D_ + j];
        else if (j < 128) sQ1[j - 64] = g_qkv[1 * F_ * D_ + i * D_ + (j - 64)];
        __syncthreads();
        const float4* __restrict__ t1 = (const float4*)&g_trans[F_ * D_ + j * D_];
        const float4* __restrict__ q0 = (const float4*)&g_qkv[j * D_];
        float dg = 0.f, dc = 0.f;
        #pragma unroll
        for (int d4 = 0; d4 < 16; ++d4) {
            const float4 a = t1[d4], b = q0[d4];
            dg += sT0[d4*4+0]*a.x + sT0[d4*4+1]*a.y + sT0[d4*4+2]*a.z + sT0[d4*4+3]*a.w;
            dc += sQ1[d4*4+0]*b.x + sQ1[d4*4+1]*b.y + sQ1[d4*4+2]*b.z + sQ1[d4*4+3]*b.w;
        }
        const float m = (dg > 0.f) ? dc : 0.f;
        const __nv_bfloat16 h = __float2bfloat16(m);
        g_Mhi[i * F_ + j] = h;
        g_Mlo[i * F_ + j] = __float2bfloat16(m - __bfloat162float(h));
    } else if (bi < 320) {
        const int d = bi - 256, j = threadIdx.x;
        g_vt[d * F_ + j] = g_qkv[2 * F_ * D_ + j * D_ + d];
    } else {
        const int tid = threadIdx.x;
        const int lane = tid & 31;
        const int warpg = (bi - 320) * 8 + (tid >> 5);
        const int row = warpg * 4 + (lane >> 3);
        const int seg = lane & 7;
        const int f = row & 255;
        const float4* fp = (const float4*)&feature[(size_t)row * D_ + seg * 8];
        const float4 f0 = fp[0], f1 = fp[1];
        float p[3];
        #pragma unroll
        for (int n = 0; n < 3; ++n) {
            const float4* qp = (const float4*)&g_qkv[n * F_ * D_ + f * D_ + seg * 8];
            const float4 q0 = qp[0], q1 = qp[1];
            float a = f0.x * q0.x + f0.y * q0.y + f0.z * q0.z + f0.w * q0.w
                    + f1.x * q1.x + f1.y * q1.y + f1.z * q1.z + f1.w * q1.w;
            a += __shfl_xor_sync(0xffffffffu, a, 1);
            a += __shfl_xor_sync(0xffffffffu, a, 2);
            a += __shfl_xor_sync(0xffffffffu, a, 4);
            p[n] = a;
        }
        if (seg == 0) {
            g_s1[row] = p[1];
            g_c [row] = p[0] * p[2];
        }
    }
}

// ---------------- kernel C: persistent HMMA GEMM, 512 thr, 4x4 warps ---------
// CTAs [0,76) -> i-half 0; [76,152) -> i-half 1. A resident once per CTA.
// Per unit (batch-pair): tile 128 rows x 128 cols, K=256 in 4 chunks of 64.
// smem: s1[512]f32 | A[2sp][128r][256k] | B[2buf][2sp][128c][64k]
#define SMS1  0u
#define SMA   2048u
#define SMB   133120u
#define SMTOT 198656u

__global__ void __launch_bounds__(512, 1) kC(float* __restrict__ out)
{
    extern __shared__ char smem[];
    const uint32_t sb = smem_u32(smem);
    const int tid = threadIdx.x, lane = tid & 31, wid = tid >> 5;
    const int wm = wid & 3;          // 4 x 32 rows
    const int wn = wid >> 2;         // 4 x 32 cols
    const int h = (blockIdx.x >= 76) ? 1 : 0;
    const int i0 = h * 128;
    const int bp0 = blockIdx.x - 76 * h;

    // ---- A fill (once per CTA): M-half hi/lo, swizzled
    #pragma unroll
    for (int sp = 0; sp < 2; ++sp) {
        const uint4* __restrict__ src = (const uint4*)(sp ? g_Mlo : g_Mhi);
        #pragma unroll
        for (int it = 0; it < 8; ++it) {
            const int idx = tid + it * 512;           // 0..4095
            const int r = idx >> 5, seg = idx & 31;
            const uint4 v = src[(i0 + r) * 32 + seg];
            const uint32_t ad = sb + SMA + (uint32_t)sp * 65536u
                              + (uint32_t)r * 512u + (uint32_t)((seg ^ (r & 7)) << 4);
            asm volatile("st.shared.v4.b32 [%0], {%1,%2,%3,%4};"
                         :: "r"(ad), "r"(v.x), "r"(v.y), "r"(v.z), "r"(v.w));
        }
    }

    // ldmatrix bases
    uint32_t aad[2]; int ax[2];
    #pragma unroll
    for (int m = 0; m < 2; ++m) {
        const int r = wm * 32 + m * 16 + (lane & 15);
        aad[m] = sb + SMA + (uint32_t)r * 512u;
        ax[m] = r & 7;
    }
    uint32_t bad[2]; int bxg[2];
    #pragma unroll
    for (int g = 0; g < 2; ++g) {
        const int r = wn * 32 + g * 16 + (lane & 15);
        bad[g] = sb + SMB + (uint32_t)r * 128u;
        bxg[g] = r & 7;
    }
    const int lk = lane >> 4;

    // B build mapping: col = tid/4 (128 cols), kq = tid&3 (16 k each)
    const int col = tid >> 2, kq = tid & 3;
    const int bd = col & 63, bbl = col >> 6;
    const uint32_t bst = sb + SMB + (uint32_t)col * 128u;
    const int bxc = col & 7;

    float* s1s = (float*)smem;

    for (int bp = bp0; bp < 512; bp += 76) {
        const int b0 = bp * 2;
        __syncthreads();                 // prior unit fully done with smem
        s1s[tid] = g_s1[(b0 + (tid >> 8)) * F_ + (tid & 255)];
        __syncthreads();

        float acc[2][4][4];
        #pragma unroll
        for (int m = 0; m < 2; ++m)
            #pragma unroll
            for (int f = 0; f < 4; ++f)
                #pragma unroll
                for (int q = 0; q < 4; ++q) acc[m][f][q] = 0.f;

#define BUILD_B(CC, BUFO) do { \
    const int jb = (CC) * 64 + kq * 16; \
    const float4* __restrict__ s1p = (const float4*)(s1s + bbl * 256 + jb); \
    const float4* __restrict__ vtp = (const float4*)(g_vt + bd * 256 + jb); \
    uint32_t uh[8], ul[8]; \
    _Pragma("unroll") \
    for (int q = 0; q < 4; ++q) { \
        const float4 sv = s1p[q], vv = vtp[q]; \
        const float H0 = sv.x * vv.x, H1 = sv.y * vv.y; \
        const float H2 = sv.z * vv.z, H3 = sv.w * vv.w; \
        uint32_t p0, p1; \
        asm("cvt.rn.bf16x2.f32 %0, %1, %2;" : "=r"(p0) : "f"(H1), "f"(H0)); \
        asm("cvt.rn.bf16x2.f32 %0, %1, %2;" : "=r"(p1) : "f"(H3), "f"(H2)); \
        uh[2*q] = p0; uh[2*q+1] = p1; \
        const float l0 = H0 - __uint_as_float(p0 << 16); \
        const float l1 = H1 - __uint_as_float(p0 & 0xffff0000u); \
        const float l2 = H2 - __uint_as_float(p1 << 16); \
        const float l3 = H3 - __uint_as_float(p1 & 0xffff0000u); \
        asm("cvt.rn.bf16x2.f32 %0, %1, %2;" : "=r"(ul[2*q])   : "f"(l1), "f"(l0)); \
        asm("cvt.rn.bf16x2.f32 %0, %1, %2;" : "=r"(ul[2*q+1]) : "f"(l3), "f"(l2)); \
    } \
    _Pragma("unroll") \
    for (int pp = 0; pp < 8; ++pp) { \
        const int p = (pp + kq) & 7; \
        const int seg = kq * 2 + (p >> 2); \
        const uint32_t ad = bst + (BUFO) + (uint32_t)((seg ^ bxc) << 4) + (uint32_t)((p & 3) << 2); \
        asm volatile("st.shared.b32 [%0], %1;" :: "r"(ad), "r"(uh[p])); \
        asm volatile("st.shared.b32 [%0], %1;" :: "r"(ad + 16384u), "r"(ul[p])); \
    } \
} while (0)

        BUILD_B(0, 0u);
        __syncthreads();

        #pragma unroll
        for (int c = 0; c < 4; ++c) {
            const uint32_t bufo = (uint32_t)(c & 1) * 32768u;
            // ---- MMA chunk c
            #pragma unroll
            for (int k16 = 0; k16 < 4; ++k16) {
                uint32_t ah[2][4], al[2][4];
                #pragma unroll
                for (int m = 0; m < 2; ++m) {
                    const int seg = c * 8 + k16 * 2 + lk;
                    const uint32_t adh = aad[m] + (uint32_t)((seg ^ ax[m]) << 4);
                    asm volatile("ldmatrix.sync.aligned.m8n8.x4.shared.b16 {%0,%1,%2,%3}, [%4];"
                                 : "=r"(ah[m][0]), "=r"(ah[m][1]), "=r"(ah[m][2]), "=r"(ah[m][3])
                                 : "r"(adh));
                    asm volatile("ldmatrix.sync.aligned.m8n8.x4.shared.b16 {%0,%1,%2,%3}, [%4];"
                                 : "=r"(al[m][0]), "=r"(al[m][1]), "=r"(al[m][2]), "=r"(al[m][3])
                                 : "r"(adh + 65536u));
                }
                #pragma unroll
                for (int g = 0; g < 2; ++g) {
                    const int seg = k16 * 2 + lk;
                    const uint32_t adb = bad[g] + bufo + (uint32_t)((seg ^ bxg[g]) << 4);
                    uint32_t hb[4], lb[4];
                    asm volatile("ldmatrix.sync.aligned.m8n8.x4.shared.b16 {%0,%1,%2,%3}, [%4];"
                                 : "=r"(hb[0]), "=r"(hb[1]), "=r"(hb[2]), "=r"(hb[3]) : "r"(adb));
                    asm volatile("ldmatrix.sync.aligned.m8n8.x4.shared.b16 {%0,%1,%2,%3}, [%4];"
                                 : "=r"(lb[0]), "=r"(lb[1]), "=r"(lb[2]), "=r"(lb[3]) : "r"(adb + 16384u));
                    #pragma unroll
                    for (int m = 0; m < 2; ++m) {
#define MMA_(ACC, AR, B0, B1) \
    asm volatile("mma.sync.aligned.m16n8k16.row.col.f32.bf16.bf16.f32 " \
        "{%0,%1,%2,%3}, {%4,%5,%6,%7}, {%8,%9}, {%0,%1,%2,%3};" \
        : "+f"(ACC[0]), "+f"(ACC[1]), "+f"(ACC[2]), "+f"(ACC[3]) \
        : "r"(AR[0]), "r"(AR[1]), "r"(AR[2]), "r"(AR[3]), "r"(B0), "r"(B1))
                        MMA_(acc[m][2*g],   ah[m], hb[0], hb[2]);
                        MMA_(acc[m][2*g+1], ah[m], hb[1], hb[3]);
                        MMA_(acc[m][2*g],   ah[m], lb[0], lb[2]);
                        MMA_(acc[m][2*g+1], ah[m], lb[1], lb[3]);
                        MMA_(acc[m][2*g],   al[m], hb[0], hb[2]);
                        MMA_(acc[m][2*g+1], al[m], hb[1], hb[3]);
#undef MMA_
                    }
                }
            }
            // ---- build next chunk into other buffer (overlaps with other warps' MMA)
            if (c < 3) {
                BUILD_B(c + 1, bufo ^ 32768u);
                __syncthreads();
            }
        }
#undef BUILD_B

        // ---- epilogue: scale by c[b,i], store
        const int b = b0 + (wn >> 1);
        const int dbw = (wn & 1) * 32;
        #pragma unroll
        for (int m = 0; m < 2; ++m) {
            const int i = i0 + wm * 32 + m * 16 + (lane >> 2);
            const float cf0 = g_c[b * F_ + i];
            const float cf1 = g_c[b * F_ + i + 8];
            float2* d0 = (float2*)&out[((size_t)b * F_ + i) * D_];
            float2* d1 = (float2*)&out[((size_t)b * F_ + i + 8) * D_];
            #pragma unroll
            for (int g = 0; g < 2; ++g)
                #pragma unroll
                for (int h8 = 0; h8 < 2; ++h8) {
                    const int d = dbw + g * 16 + h8 * 8 + (lane & 3) * 2;
                    const float* A4 = acc[m][2*g + h8];
                    d0[d >> 1] = make_float2(A4[0] * cf0, A4[1] * cf0);
                    d1[d >> 1] = make_float2(A4[2] * cf1, A4[3] * cf1);
                }
        }
    }
}

// ---------------- launch ------------------------------------------------------
extern "C" void kernel_launch(void* const* d_in, const int* in_sizes, int n_in,
                              void* d_out, int out_size)
{
    const float* feature   = (const float*)d_in[0];
    const float* indicator = (const float*)d_in[1];
    const float* W_qk      = (const float*)d_in[2];
    const float* W_qkv     = (const float*)d_in[3];
    float* out = (float*)d_out;

    cudaFuncSetAttribute(kC, cudaFuncAttributeMaxDynamicSharedMemorySize, SMTOT);

    kA1<<<F_, 320>>>(indicator, W_qk, W_qkv);
    kAB<<<320 + (B_ * F_) / 32, 256>>>(feature);
    kC<<<152, 512, SMTOT>>>(out);
}

// round 6
// speedup vs baseline: 3.0173x; 1.0319x over previous
#include <cuda_runtime.h>
#include <cuda_bf16.h>
#include <cstdint>

#define B_  1024
#define F_  256
#define D_  64

// ---------------- scratch (device globals) -----------------------------------
__device__ float g_trans[2 * F_ * D_];
__device__ float g_qkv  [3 * F_ * D_];
__device__ float g_vt   [D_ * F_];                 // V transposed [d][j]
__device__ float g_c    [B_ * F_];
__device__ __nv_bfloat16 g_s1hi[B_ * F_];
__device__ __nv_bfloat16 g_s1lo[B_ * F_];
__device__ __nv_bfloat16 g_Khi[F_ * D_ * F_];      // [(i*64+d)][j]
__device__ __nv_bfloat16 g_Klo[F_ * D_ * F_];

__device__ __forceinline__ uint32_t smem_u32(const void* p) {
    uint32_t a;
    asm("{ .reg .u64 t; cvta.to.shared.u64 t, %1; cvt.u32.u64 %0, t; }" : "=r"(a) : "l"(p));
    return a;
}

// ---------------- kernel A1: trans & qkv (+ V transpose) ---------------------
__global__ void kA1(const float* __restrict__ ind,
                    const float* __restrict__ Wqk,
                    const float* __restrict__ Wqkv)
{
    __shared__ float sInd[D_];
    const int f = blockIdx.x, t = threadIdx.x;
    const int n = t >> 6, e = t & 63;
    if (t < 64) sInd[t] = ind[f * D_ + t];
    __syncthreads();
    const float* __restrict__ W = (n < 2) ? (Wqk + n * D_ * D_) : (Wqkv + (n - 2) * D_ * D_);
    float acc = 0.f;
    #pragma unroll 16
    for (int d = 0; d < D_; ++d) acc = fmaf(sInd[d], W[d * D_ + e], acc);
    if (n < 2) g_trans[n * F_ * D_ + f * D_ + e] = acc;
    else {
        g_qkv[(n - 2) * F_ * D_ + f * D_ + e] = acc;
        if (n == 4) g_vt[e * F_ + f] = acc;        // V^T for K build
    }
}

// ------ kernel AB: blocks [0,256) build K matrix; rest = s pass --------------
__global__ void kAB(const float* __restrict__ feature)
{
    const int bi = blockIdx.x;
    if (bi < 256) {
        // M[i,j] = (trans0_i.trans1_j > 0) ? qkv1_i.qkv0_j : 0
        __shared__ float sT0[D_];
        __shared__ float sQ1[D_];
        const int i = bi;
        const int j = threadIdx.x;
        if (j < 64)       sT0[j]      = g_trans[i * D_ + j];
        else if (j < 128) sQ1[j - 64] = g_qkv[1 * F_ * D_ + i * D_ + (j - 64)];
        __syncthreads();
        const float4* __restrict__ t1 = (const float4*)&g_trans[F_ * D_ + j * D_];
        const float4* __restrict__ q0 = (const float4*)&g_qkv[j * D_];
        float dg = 0.f, dc = 0.f;
        #pragma unroll
        for (int d4 = 0; d4 < 16; ++d4) {
            const float4 a = t1[d4], b = q0[d4];
            dg += sT0[d4*4+0]*a.x + sT0[d4*4+1]*a.y + sT0[d4*4+2]*a.z + sT0[d4*4+3]*a.w;
            dc += sQ1[d4*4+0]*b.x + sQ1[d4*4+1]*b.y + sQ1[d4*4+2]*b.z + sQ1[d4*4+3]*b.w;
        }
        const float m = (dg > 0.f) ? dc : 0.f;
        // K[(i,d)][j] = m * V[j][d], split hi/lo
        #pragma unroll 8
        for (int d = 0; d < 64; ++d) {
            const float kv = m * g_vt[d * F_ + j];
            const __nv_bfloat16 h = __float2bfloat16(kv);
            g_Khi[(i * 64 + d) * F_ + j] = h;
            g_Klo[(i * 64 + d) * F_ + j] = __float2bfloat16(kv - __bfloat162float(h));
        }
    } else {
        const int tid = threadIdx.x;
        const int lane = tid & 31;
        const int warpg = (bi - 256) * 8 + (tid >> 5);
        const int row = warpg * 4 + (lane >> 3);
        const int seg = lane & 7;
        const int f = row & 255;
        const float4* fp = (const float4*)&feature[(size_t)row * D_ + seg * 8];
        const float4 f0 = fp[0], f1 = fp[1];
        float p[3];
        #pragma unroll
        for (int n = 0; n < 3; ++n) {
            const float4* qp = (const float4*)&g_qkv[n * F_ * D_ + f * D_ + seg * 8];
            const float4 q0 = qp[0], q1 = qp[1];
            float a = f0.x * q0.x + f0.y * q0.y + f0.z * q0.z + f0.w * q0.w
                    + f1.x * q1.x + f1.y * q1.y + f1.z * q1.z + f1.w * q1.w;
            a += __shfl_xor_sync(0xffffffffu, a, 1);
            a += __shfl_xor_sync(0xffffffffu, a, 2);
            a += __shfl_xor_sync(0xffffffffu, a, 4);
            p[n] = a;
        }
        if (seg == 0) {
            const float s1v = p[1];
            const __nv_bfloat16 h = __float2bfloat16(s1v);
            g_s1hi[row] = h;
            g_s1lo[row] = __float2bfloat16(s1v - __bfloat162float(h));
            g_c[row] = p[0] * p[2];
        }
    }
}

// ---------------- kernel G: C[1024,16384] = s1 x K^T (split-3 bf16) ----------
// CTA tile: 128 b x 256 n, K=256 in 4 chunks of 64, cp.async double-buffer.
// Warps: 2 m x 8 n, warp tile 64 b x 32 n.
#define SA_HI 0u
#define SA_LO 16384u
#define SB_HI 32768u
#define SB_LO 65536u
#define BUFSZ 98304u
#define SMTOT 196608u

#define CP16(DST, SRC) \
    asm volatile("cp.async.cg.shared.global [%0], [%1], 16;" :: "r"(DST), "l"(SRC))

#define ISSUE_CHUNK(C, BO) do { \
    _Pragma("unroll") \
    for (int sp = 0; sp < 2; ++sp) { \
        const __nv_bfloat16* __restrict__ asrc = sp ? g_s1lo : g_s1hi; \
        _Pragma("unroll") \
        for (int it = 0; it < 2; ++it) { \
            const int idx = tid + it * 512; \
            const int r = idx >> 3, sg = idx & 7; \
            const uint32_t dst = sb + (BO) + (sp ? SA_LO : SA_HI) \
                               + (uint32_t)r * 128u + (uint32_t)((sg ^ (r & 7)) << 4); \
            CP16(dst, asrc + (b0 + r) * F_ + (C) * 64 + sg * 8); \
        } \
        const __nv_bfloat16* __restrict__ bsrc = sp ? g_Klo : g_Khi; \
        _Pragma("unroll") \
        for (int it = 0; it < 4; ++it) { \
            const int idx = tid + it * 512; \
            const int r = idx >> 3, sg = idx & 7; \
            const uint32_t dst = sb + (BO) + (sp ? SB_LO : SB_HI) \
                               + (uint32_t)r * 128u + (uint32_t)((sg ^ (r & 7)) << 4); \
            CP16(dst, bsrc + (n0 + r) * F_ + (C) * 64 + sg * 8); \
        } \
    } \
    asm volatile("cp.async.commit_group;" ::: "memory"); \
} while (0)

__global__ void __launch_bounds__(512, 1) kG(float* __restrict__ out)
{
    extern __shared__ char smem[];
    const uint32_t sb = smem_u32(smem);
    const int tid = threadIdx.x, lane = tid & 31, wid = tid >> 5;
    const int wm = wid >> 3;         // 2 m-warps (64 b each)
    const int wn = wid & 7;          // 8 n-warps (32 n each)
    const int b0 = blockIdx.y * 128;
    const int n0 = blockIdx.x * 256;

    ISSUE_CHUNK(0, 0u);
    ISSUE_CHUNK(1, BUFSZ);

    float acc[4][4][4];
    #pragma unroll
    for (int f = 0; f < 4; ++f)
        #pragma unroll
        for (int g = 0; g < 4; ++g)
            #pragma unroll
            for (int q = 0; q < 4; ++q) acc[f][g][q] = 0.f;

    // ldmatrix base components
    uint32_t aad[4]; int axr[4];
    #pragma unroll
    for (int f = 0; f < 4; ++f) {
        const int r = wm * 64 + f * 16 + (lane & 15);
        aad[f] = sb + SA_HI + (uint32_t)r * 128u;
        axr[f] = r & 7;
    }
    uint32_t bad[2]; int bxr[2];
    #pragma unroll
    for (int g = 0; g < 2; ++g) {
        const int r = wn * 32 + g * 16 + (lane & 15);
        bad[g] = sb + SB_HI + (uint32_t)r * 128u;
        bxr[g] = r & 7;
    }
    const int lk = lane >> 4;

    #pragma unroll
    for (int c = 0; c < 4; ++c) {
        if (c < 3) asm volatile("cp.async.wait_group 1;" ::: "memory");
        else       asm volatile("cp.async.wait_group 0;" ::: "memory");
        __syncthreads();
        const uint32_t bo = (uint32_t)(c & 1) * BUFSZ;

        #pragma unroll
        for (int k16 = 0; k16 < 4; ++k16) {
            const int sg = k16 * 2 + lk;
            uint32_t Ah[4][4], Al[4][4];
            #pragma unroll
            for (int f = 0; f < 4; ++f) {
                const uint32_t ad = aad[f] + bo + (uint32_t)((sg ^ axr[f]) << 4);
                asm volatile("ldmatrix.sync.aligned.m8n8.x4.shared.b16 {%0,%1,%2,%3}, [%4];"
                             : "=r"(Ah[f][0]), "=r"(Ah[f][1]), "=r"(Ah[f][2]), "=r"(Ah[f][3])
                             : "r"(ad));
                asm volatile("ldmatrix.sync.aligned.m8n8.x4.shared.b16 {%0,%1,%2,%3}, [%4];"
                             : "=r"(Al[f][0]), "=r"(Al[f][1]), "=r"(Al[f][2]), "=r"(Al[f][3])
                             : "r"(ad + 16384u));
            }
            #pragma unroll
            for (int g = 0; g < 2; ++g) {
                const uint32_t ad = bad[g] + bo + (uint32_t)((sg ^ bxr[g]) << 4);
                uint32_t Bh[4], Bl[4];
                asm volatile("ldmatrix.sync.aligned.m8n8.x4.shared.b16 {%0,%1,%2,%3}, [%4];"
                             : "=r"(Bh[0]), "=r"(Bh[1]), "=r"(Bh[2]), "=r"(Bh[3]) : "r"(ad));
                asm volatile("ldmatrix.sync.aligned.m8n8.x4.shared.b16 {%0,%1,%2,%3}, [%4];"
                             : "=r"(Bl[0]), "=r"(Bl[1]), "=r"(Bl[2]), "=r"(Bl[3]) : "r"(ad + 32768u));
#define MMA_(ACC, AR, B0r, B1r) \
    asm volatile("mma.sync.aligned.m16n8k16.row.col.f32.bf16.bf16.f32 " \
        "{%0,%1,%2,%3}, {%4,%5,%6,%7}, {%8,%9}, {%0,%1,%2,%3};" \
        : "+f"(ACC[0]), "+f"(ACC[1]), "+f"(ACC[2]), "+f"(ACC[3]) \
        : "r"(AR[0]), "r"(AR[1]), "r"(AR[2]), "r"(AR[3]), "r"(B0r), "r"(B1r))
                #pragma unroll
                for (int f = 0; f < 4; ++f) {
                    MMA_(acc[f][2*g],   Ah[f], Bh[0], Bh[2]);
                    MMA_(acc[f][2*g+1], Ah[f], Bh[1], Bh[3]);
                }
                #pragma unroll
                for (int f = 0; f < 4; ++f) {
                    MMA_(acc[f][2*g],   Ah[f], Bl[0], Bl[2]);
                    MMA_(acc[f][2*g+1], Ah[f], Bl[1], Bl[3]);
                }
                #pragma unroll
                for (int f = 0; f < 4; ++f) {
                    MMA_(acc[f][2*g],   Al[f], Bh[0], Bh[2]);
                    MMA_(acc[f][2*g+1], Al[f], Bh[1], Bh[3]);
                }
#undef MMA_
            }
        }
        __syncthreads();
        if (c < 2) ISSUE_CHUNK(c + 2, bo);
    }

    // ---- epilogue: scale by c[b,i], coalesced-ish float2 stores
    const int iw = (n0 >> 6) + (wn >> 1);          // this warp's single i
    #pragma unroll
    for (int f = 0; f < 4; ++f) {
        const int br0 = b0 + wm * 64 + f * 16 + (lane >> 2);
        const float cf0 = g_c[br0 * F_ + iw];
        const float cf1 = g_c[(br0 + 8) * F_ + iw];
        float* o0 = out + (size_t)br0 * 16384 + n0 + wn * 32;
        float* o1 = out + (size_t)(br0 + 8) * 16384 + n0 + wn * 32;
        #pragma unroll
        for (int g = 0; g < 2; ++g)
            #pragma unroll
            for (int h = 0; h < 2; ++h) {
                const int dn = g * 16 + h * 8 + (lane & 3) * 2;
                const float* a4 = acc[f][2*g + h];
                *(float2*)(o0 + dn) = make_float2(a4[0] * cf0, a4[1] * cf0);
                *(float2*)(o1 + dn) = make_float2(a4[2] * cf1, a4[3] * cf1);
            }
    }
}

// ---------------- launch ------------------------------------------------------
extern "C" void kernel_launch(void* const* d_in, const int* in_sizes, int n_in,
                              void* d_out, int out_size)
{
    const float* feature   = (const float*)d_in[0];
    const float* indicator = (const float*)d_in[1];
    const float* W_qk      = (const float*)d_in[2];
    const float* W_qkv     = (const float*)d_in[3];
    float* out = (float*)d_out;

    cudaFuncSetAttribute(kG, cudaFuncAttributeMaxDynamicSharedMemorySize, SMTOT);

    kA1<<<F_, 320>>>(indicator, W_qk, W_qkv);
    kAB<<<256 + (B_ * F_) / 32, 256>>>(feature);
    kG<<<dim3(64, 8), 512, SMTOT>>>(out);
}

// round 9
// speedup vs baseline: 4.0404x; 1.3391x over previous
#include <cuda_runtime.h>
#include <cuda_fp16.h>
#include <cstdint>

#define B_  1024
#define F_  256
#define D_  64

// ---------------- scratch (device globals) -----------------------------------
__device__ float g_trans[2 * F_ * D_];
__device__ float g_qkv  [3 * F_ * D_];
__device__ float g_vt   [D_ * F_];                 // V transposed [d][j]
__device__ float g_c    [B_ * F_];
__device__ __half g_s1hi[B_ * F_];
__device__ __half g_s1lo[B_ * F_];
__device__ __half g_Kh  [F_ * D_ * F_];            // [(i*64+d)][j] fp16

__device__ __forceinline__ uint32_t smem_u32(const void* p) {
    uint32_t a;
    asm("{ .reg .u64 t; cvta.to.shared.u64 t, %1; cvt.u32.u64 %0, t; }" : "=r"(a) : "l"(p));
    return a;
}

// ---------------- kernel A1: trans & qkv (+ V transpose) ---------------------
__global__ void kA1(const float* __restrict__ ind,
                    const float* __restrict__ Wqk,
                    const float* __restrict__ Wqkv)
{
    __shared__ float sInd[D_];
    const int f = blockIdx.x, t = threadIdx.x;
    const int n = t >> 6, e = t & 63;
    if (t < 64) sInd[t] = ind[f * D_ + t];
    __syncthreads();
    const float* __restrict__ W = (n < 2) ? (Wqk + n * D_ * D_) : (Wqkv + (n - 2) * D_ * D_);
    float acc = 0.f;
    #pragma unroll 16
    for (int d = 0; d < D_; ++d) acc = fmaf(sInd[d], W[d * D_ + e], acc);
    if (n < 2) g_trans[n * F_ * D_ + f * D_ + e] = acc;
    else {
        g_qkv[(n - 2) * F_ * D_ + f * D_ + e] = acc;
        if (n == 4) g_vt[e * F_ + f] = acc;        // V^T for K build
    }
}

// ------ kernel AB: blocks [0,512) build K matrix; rest = s pass --------------
__global__ void kAB(const float* __restrict__ feature)
{
    const int bi = blockIdx.x;
    if (bi < 512) {
        // M[i,j] = (trans0_i.trans1_j > 0) ? qkv1_i.qkv0_j : 0 ; K = M*V fp16
        __shared__ float sT0[D_];
        __shared__ float sQ1[D_];
        const int i = bi >> 1, d0 = (bi & 1) * 32;
        const int j = threadIdx.x;
        if (j < 64)       sT0[j]      = g_trans[i * D_ + j];
        else if (j < 128) sQ1[j - 64] = g_qkv[1 * F_ * D_ + i * D_ + (j - 64)];
        __syncthreads();
        const float4* __restrict__ t1 = (const float4*)&g_trans[F_ * D_ + j * D_];
        const float4* __restrict__ q0 = (const float4*)&g_qkv[j * D_];
        float dg = 0.f, dc = 0.f;
        #pragma unroll
        for (int d4 = 0; d4 < 16; ++d4) {
            const float4 a = t1[d4], b = q0[d4];
            dg += sT0[d4*4+0]*a.x + sT0[d4*4+1]*a.y + sT0[d4*4+2]*a.z + sT0[d4*4+3]*a.w;
            dc += sQ1[d4*4+0]*b.x + sQ1[d4*4+1]*b.y + sQ1[d4*4+2]*b.z + sQ1[d4*4+3]*b.w;
        }
        const float m = (dg > 0.f) ? dc : 0.f;
        #pragma unroll 8
        for (int dd = 0; dd < 32; ++dd) {
            const int d = d0 + dd;
            g_Kh[(i * 64 + d) * F_ + j] = __float2half_rn(m * g_vt[d * F_ + j]);
        }
    } else {
        const int tid = threadIdx.x;
        const int lane = tid & 31;
        const int warpg = (bi - 512) * 8 + (tid >> 5);
        const int row = warpg * 4 + (lane >> 3);
        const int seg = lane & 7;
        const int f = row & 255;
        const float4* fp = (const float4*)&feature[(size_t)row * D_ + seg * 8];
        const float4 f0 = fp[0], f1 = fp[1];
        float p[3];
        #pragma unroll
        for (int n = 0; n < 3; ++n) {
            const float4* qp = (const float4*)&g_qkv[n * F_ * D_ + f * D_ + seg * 8];
            const float4 q0 = qp[0], q1 = qp[1];
            float a = f0.x * q0.x + f0.y * q0.y + f0.z * q0.z + f0.w * q0.w
                    + f1.x * q1.x + f1.y * q1.y + f1.z * q1.z + f1.w * q1.w;
            a += __shfl_xor_sync(0xffffffffu, a, 1);
            a += __shfl_xor_sync(0xffffffffu, a, 2);
            a += __shfl_xor_sync(0xffffffffu, a, 4);
            p[n] = a;
        }
        if (seg == 0) {
            const float s1v = p[1];
            const __half h = __float2half_rn(s1v);
            g_s1hi[row] = h;
            g_s1lo[row] = __float2half_rn(s1v - __half2float(h));
            g_c[row] = p[0] * p[2];
        }
    }
}

// ---------------- kernel G: C[1024,16384] = s1 x K^T  (fp16, 2-MMA split) ----
// CTA tile: 64 b x 256 n, K=256 in 4 chunks of 64, cp.async double-buffer.
// 8 warps (2m x 4n), warp tile 32 b x 64 n. 2 CTAs/SM.
#define SA_HI 0u
#define SA_LO 8192u
#define SB    16384u
#define BUFSZ 49152u
#define SMTOT 98304u

#define CP16(DST, SRC) \
    asm volatile("cp.async.cg.shared.global [%0], [%1], 16;" :: "r"(DST), "l"(SRC))

#define ISSUE_CHUNK(C, BO) do { \
    _Pragma("unroll") \
    for (int sp = 0; sp < 2; ++sp) { \
        const __half* __restrict__ asrc = sp ? g_s1lo : g_s1hi; \
        _Pragma("unroll") \
        for (int it = 0; it < 2; ++it) { \
            const int idx = tid + it * 256; \
            const int r = idx >> 3, sg = idx & 7; \
            const uint32_t dst = sb + (BO) + (sp ? SA_LO : SA_HI) \
                               + (uint32_t)r * 128u + (uint32_t)((sg ^ (r & 7)) << 4); \
            CP16(dst, asrc + (b0 + r) * F_ + (C) * 64 + sg * 8); \
        } \
    } \
    _Pragma("unroll") \
    for (int it = 0; it < 8; ++it) { \
        const int idx = tid + it * 256; \
        const int r = idx >> 3, sg = idx & 7; \
        const uint32_t dst = sb + (BO) + SB \
                           + (uint32_t)r * 128u + (uint32_t)((sg ^ (r & 7)) << 4); \
        CP16(dst, g_Kh + (n0 + r) * F_ + (C) * 64 + sg * 8); \
    } \
    asm volatile("cp.async.commit_group;" ::: "memory"); \
} while (0)

__global__ void __launch_bounds__(256, 2) kG(float* __restrict__ out)
{
    extern __shared__ char smem[];
    const uint32_t sb = smem_u32(smem);
    const int tid = threadIdx.x, lane = tid & 31, wid = tid >> 5;
    const int wm = wid >> 2;         // 2 m-warps (32 b each)
    const int wn = wid & 3;          // 4 n-warps (64 n each)
    const int b0 = blockIdx.y * 64;
    const int n0 = blockIdx.x * 256;

    ISSUE_CHUNK(0, 0u);
    ISSUE_CHUNK(1, BUFSZ);

    float acc[2][8][4];
    #pragma unroll
    for (int f = 0; f < 2; ++f)
        #pragma unroll
        for (int g = 0; g < 8; ++g)
            #pragma unroll
            for (int q = 0; q < 4; ++q) acc[f][g][q] = 0.f;

    uint32_t aad[2]; int axr[2];
    #pragma unroll
    for (int f = 0; f < 2; ++f) {
        const int r = wm * 32 + f * 16 + (lane & 15);
        aad[f] = sb + (uint32_t)r * 128u;
        axr[f] = r & 7;
    }
    uint32_t bad[4]; int bxr[4];
    #pragma unroll
    for (int g = 0; g < 4; ++g) {
        const int r = wn * 64 + g * 16 + (lane & 15);
        bad[g] = sb + SB + (uint32_t)r * 128u;
        bxr[g] = r & 7;
    }
    const int lk = lane >> 4;

    #pragma unroll
    for (int c = 0; c < 4; ++c) {
        if (c < 3) asm volatile("cp.async.wait_group 1;" ::: "memory");
        else       asm volatile("cp.async.wait_group 0;" ::: "memory");
        __syncthreads();
        const uint32_t bo = (uint32_t)(c & 1) * BUFSZ;

        #pragma unroll
        for (int k16 = 0; k16 < 4; ++k16) {
            const int sg = k16 * 2 + lk;
            uint32_t Ah[2][4], Al[2][4];
            #pragma unroll
            for (int f = 0; f < 2; ++f) {
                const uint32_t ad = aad[f] + bo + (uint32_t)((sg ^ axr[f]) << 4);
                asm volatile("ldmatrix.sync.aligned.m8n8.x4.shared.b16 {%0,%1,%2,%3}, [%4];"
                             : "=r"(Ah[f][0]), "=r"(Ah[f][1]), "=r"(Ah[f][2]), "=r"(Ah[f][3])
                             : "r"(ad));
                asm volatile("ldmatrix.sync.aligned.m8n8.x4.shared.b16 {%0,%1,%2,%3}, [%4];"
                             : "=r"(Al[f][0]), "=r"(Al[f][1]), "=r"(Al[f][2]), "=r"(Al[f][3])
                             : "r"(ad + 8192u));
            }
            #pragma unroll
            for (int g = 0; g < 4; ++g) {
                const uint32_t ad = bad[g] + bo + (uint32_t)((sg ^ bxr[g]) << 4);
                uint32_t Bh[4];
                asm volatile("ldmatrix.sync.aligned.m8n8.x4.shared.b16 {%0,%1,%2,%3}, [%4];"
                             : "=r"(Bh[0]), "=r"(Bh[1]), "=r"(Bh[2]), "=r"(Bh[3]) : "r"(ad));
#define MMA_(ACC, AR, B0r, B1r) \
    asm volatile("mma.sync.aligned.m16n8k16.row.col.f32.f16.f16.f32 " \
        "{%0,%1,%2,%3}, {%4,%5,%6,%7}, {%8,%9}, {%0,%1,%2,%3};" \
        : "+f"(ACC[0]), "+f"(ACC[1]), "+f"(ACC[2]), "+f"(ACC[3]) \
        : "r"(AR[0]), "r"(AR[1]), "r"(AR[2]), "r"(AR[3]), "r"(B0r), "r"(B1r))
                #pragma unroll
                for (int f = 0; f < 2; ++f) {
                    MMA_(acc[f][2*g],   Ah[f], Bh[0], Bh[2]);
                    MMA_(acc[f][2*g+1], Ah[f], Bh[1], Bh[3]);
                    MMA_(acc[f][2*g],   Al[f], Bh[0], Bh[2]);
                    MMA_(acc[f][2*g+1], Al[f], Bh[1], Bh[3]);
                }
#undef MMA_
            }
        }
        __syncthreads();
        if (c < 2) ISSUE_CHUNK(c + 2, bo);
    }

    // ---- epilogue: scale by c[b,i], store
    const int iw = (n0 >> 6) + wn;                 // this warp's single i
    #pragma unroll
    for (int f = 0; f < 2; ++f) {
        const int br0 = b0 + wm * 32 + f * 16 + (lane >> 2);
        const float cf0 = g_c[br0 * F_ + iw];
        const float cf1 = g_c[(br0 + 8) * F_ + iw];
        float* o0 = out + (size_t)br0 * 16384 + n0 + wn * 64;
        float* o1 = out + (size_t)(br0 + 8) * 16384 + n0 + wn * 64;
        #pragma unroll
        for (int g = 0; g < 4; ++g)
            #pragma unroll
            for (int h8 = 0; h8 < 2; ++h8) {
                const int dn = g * 16 + h8 * 8 + (lane & 3) * 2;
                const float* a4 = acc[f][2*g + h8];
                *(float2*)(o0 + dn) = make_float2(a4[0] * cf0, a4[1] * cf0);
                *(float2*)(o1 + dn) = make_float2(a4[2] * cf1, a4[3] * cf1);
            }
    }
}

// ---------------- launch ------------------------------------------------------
extern "C" void kernel_launch(void* const* d_in, const int* in_sizes, int n_in,
                              void* d_out, int out_size)
{
    const float* feature   = (const float*)d_in[0];
    const float* indicator = (const float*)d_in[1];
    const float* W_qk      = (const float*)d_in[2];
    const float* W_qkv     = (const float*)d_in[3];
    float* out = (float*)d_out;

    cudaFuncSetAttribute(kG, cudaFuncAttributeMaxDynamicSharedMemorySize, SMTOT);

    kA1<<<F_, 320>>>(indicator, W_qk, W_qkv);
    kAB<<<512 + (B_ * F_) / 32, 256>>>(feature);
    kG<<<dim3(64, 16), 256, SMTOT>>>(out);
}

// round 14
// speedup vs baseline: 5.1062x; 1.2638x over previous
#include <cuda_runtime.h>
#include <cuda_fp16.h>
#include <cstdint>

#define B_  1024
#define F_  256
#define D_  64

// ---------------- scratch (device globals) -----------------------------------
__device__ float g_trans[2 * F_ * D_];
__device__ float g_qkv  [3 * F_ * D_];
__device__ float g_vt   [D_ * F_];                 // V transposed [d][j]
__device__ float g_c    [B_ * F_];
__device__ __half g_s1h [B_ * F_];
__device__ __half g_Kh  [F_ * D_ * F_];            // [(i*64+d)][j] fp16

__device__ __forceinline__ uint32_t smem_u32(const void* p) {
    uint32_t a;
    asm("{ .reg .u64 t; cvta.to.shared.u64 t, %1; cvt.u32.u64 %0, t; }" : "=r"(a) : "l"(p));
    return a;
}

// ---------------- kernel A1: trans & qkv (+ V transpose) ---------------------
__global__ void kA1(const float* __restrict__ ind,
                    const float* __restrict__ Wqk,
                    const float* __restrict__ Wqkv)
{
    __shared__ float sInd[D_];
    const int f = blockIdx.x, t = threadIdx.x;
    const int n = t >> 6, e = t & 63;
    if (t < 64) sInd[t] = ind[f * D_ + t];
    __syncthreads();
    const float* __restrict__ W = (n < 2) ? (Wqk + n * D_ * D_) : (Wqkv + (n - 2) * D_ * D_);
    // 4 partial accumulators: breaks the serial FMA chain, 4x MLP
    float a0 = 0.f, a1 = 0.f, a2 = 0.f, a3 = 0.f;
    #pragma unroll
    for (int d = 0; d < D_; d += 4) {
        a0 = fmaf(sInd[d + 0], W[(d + 0) * D_ + e], a0);
        a1 = fmaf(sInd[d + 1], W[(d + 1) * D_ + e], a1);
        a2 = fmaf(sInd[d + 2], W[(d + 2) * D_ + e], a2);
        a3 = fmaf(sInd[d + 3], W[(d + 3) * D_ + e], a3);
    }
    const float acc = (a0 + a1) + (a2 + a3);
    if (n < 2) g_trans[n * F_ * D_ + f * D_ + e] = acc;
    else {
        g_qkv[(n - 2) * F_ * D_ + f * D_ + e] = acc;
        if (n == 4) g_vt[e * F_ + f] = acc;        // V^T for K build
    }
}

// ------ kernel AB: blocks [0,512) build K matrix; rest = s pass --------------
__global__ void kAB(const float* __restrict__ feature)
{
    const int bi = blockIdx.x;
    if (bi < 512) {
        // M[i,j] = (trans0_i.trans1_j > 0) ? qkv1_i.qkv0_j : 0 ; K = M*V fp16
        __shared__ float sT0[D_];
        __shared__ float sQ1[D_];
        const int i = bi >> 1, d0 = (bi & 1) * 32;
        const int j = threadIdx.x;
        if (j < 64)       sT0[j]      = g_trans[i * D_ + j];
        else if (j < 128) sQ1[j - 64] = g_qkv[1 * F_ * D_ + i * D_ + (j - 64)];
        __syncthreads();
        const float4* __restrict__ t1 = (const float4*)&g_trans[F_ * D_ + j * D_];
        const float4* __restrict__ q0 = (const float4*)&g_qkv[j * D_];
        float dg = 0.f, dc = 0.f;
        #pragma unroll
        for (int d4 = 0; d4 < 16; ++d4) {
            const float4 a = t1[d4], b = q0[d4];
            dg += sT0[d4*4+0]*a.x + sT0[d4*4+1]*a.y + sT0[d4*4+2]*a.z + sT0[d4*4+3]*a.w;
            dc += sQ1[d4*4+0]*b.x + sQ1[d4*4+1]*b.y + sQ1[d4*4+2]*b.z + sQ1[d4*4+3]*b.w;
        }
        const float m = (dg > 0.f) ? dc : 0.f;
        #pragma unroll 8
        for (int dd = 0; dd < 32; ++dd) {
            const int d = d0 + dd;
            g_Kh[(i * 64 + d) * F_ + j] = __float2half_rn(m * g_vt[d * F_ + j]);
        }
    } else {
        const int tid = threadIdx.x;
        const int lane = tid & 31;
        const int warpg = (bi - 512) * 8 + (tid >> 5);
        const int row = warpg * 4 + (lane >> 3);
        const int seg = lane & 7;
        const int f = row & 255;
        const float4* fp = (const float4*)&feature[(size_t)row * D_ + seg * 8];
        const float4 f0 = fp[0], f1 = fp[1];
        float p[3];
        #pragma unroll
        for (int n = 0; n < 3; ++n) {
            const float4* qp = (const float4*)&g_qkv[n * F_ * D_ + f * D_ + seg * 8];
            const float4 q0 = qp[0], q1 = qp[1];
            float a = f0.x * q0.x + f0.y * q0.y + f0.z * q0.z + f0.w * q0.w
                    + f1.x * q1.x + f1.y * q1.y + f1.z * q1.z + f1.w * q1.w;
            a += __shfl_xor_sync(0xffffffffu, a, 1);
            a += __shfl_xor_sync(0xffffffffu, a, 2);
            a += __shfl_xor_sync(0xffffffffu, a, 4);
            p[n] = a;
        }
        if (seg == 0) {
            g_s1h[row] = __float2half_rn(p[1]);
            g_c[row] = p[0] * p[2];
        }
    }
}

// ---------------- kernel G: C[1024,16384] = s1 x K^T  (single fp16) ----------
// CTA tile: 64 b x 256 n, K=256 in 4 chunks of 64, cp.async double-buffer.
// 8 warps (2m x 4n), warp tile 32 b x 64 n. 2 CTAs/SM.
#define SA    0u
#define SB    8192u
#define BUFSZ 40960u
#define SMTOT 81920u

#define CP16(DST, SRC) \
    asm volatile("cp.async.cg.shared.global [%0], [%1], 16;" :: "r"(DST), "l"(SRC))

#define ISSUE_CHUNK(C, BO) do { \
    _Pragma("unroll") \
    for (int it = 0; it < 2; ++it) { \
        const int idx = tid + it * 256; \
        const int r = idx >> 3, sg = idx & 7; \
        const uint32_t dst = sb + (BO) + SA \
                           + (uint32_t)r * 128u + (uint32_t)((sg ^ (r & 7)) << 4); \
        CP16(dst, g_s1h + (b0 + r) * F_ + (C) * 64 + sg * 8); \
    } \
    _Pragma("unroll") \
    for (int it = 0; it < 8; ++it) { \
        const int idx = tid + it * 256; \
        const int r = idx >> 3, sg = idx & 7; \
        const uint32_t dst = sb + (BO) + SB \
                           + (uint32_t)r * 128u + (uint32_t)((sg ^ (r & 7)) << 4); \
        CP16(dst, g_Kh + (n0 + r) * F_ + (C) * 64 + sg * 8); \
    } \
    asm volatile("cp.async.commit_group;" ::: "memory"); \
} while (0)

__global__ void __launch_bounds__(256, 2) kG(float* __restrict__ out)
{
    extern __shared__ char smem[];
    const uint32_t sb = smem_u32(smem);
    const int tid = threadIdx.x, lane = tid & 31, wid = tid >> 5;
    const int wm = wid >> 2;         // 2 m-warps (32 b each)
    const int wn = wid & 3;          // 4 n-warps (64 n each)
    const int b0 = blockIdx.y * 64;
    const int n0 = blockIdx.x * 256;

    ISSUE_CHUNK(0, 0u);
    ISSUE_CHUNK(1, BUFSZ);

    float acc[2][8][4];
    #pragma unroll
    for (int f = 0; f < 2; ++f)
        #pragma unroll
        for (int g = 0; g < 8; ++g)
            #pragma unroll
            for (int q = 0; q < 4; ++q) acc[f][g][q] = 0.f;

    uint32_t aad[2]; int axr[2];
    #pragma unroll
    for (int f = 0; f < 2; ++f) {
        const int r = wm * 32 + f * 16 + (lane & 15);
        aad[f] = sb + SA + (uint32_t)r * 128u;
        axr[f] = r & 7;
    }
    uint32_t bad[4]; int bxr[4];
    #pragma unroll
    for (int g = 0; g < 4; ++g) {
        const int r = wn * 64 + g * 16 + (lane & 15);
        bad[g] = sb + SB + (uint32_t)r * 128u;
        bxr[g] = r & 7;
    }
    const int lk = lane >> 4;

    #pragma unroll
    for (int c = 0; c < 4; ++c) {
        if (c < 3) asm volatile("cp.async.wait_group 1;" ::: "memory");
        else       asm volatile("cp.async.wait_group 0;" ::: "memory");
        __syncthreads();
        const uint32_t bo = (uint32_t)(c & 1) * BUFSZ;

        #pragma unroll
        for (int k16 = 0; k16 < 4; ++k16) {
            const int sg = k16 * 2 + lk;
            uint32_t Ah[2][4];
            #pragma unroll
            for (int f = 0; f < 2; ++f) {
                const uint32_t ad = aad[f] + bo + (uint32_t)((sg ^ axr[f]) << 4);
                asm volatile("ldmatrix.sync.aligned.m8n8.x4.shared.b16 {%0,%1,%2,%3}, [%4];"
                             : "=r"(Ah[f][0]), "=r"(Ah[f][1]), "=r"(Ah[f][2]), "=r"(Ah[f][3])
                             : "r"(ad));
            }
            #pragma unroll
            for (int g = 0; g < 4; ++g) {
                const uint32_t ad = bad[g] + bo + (uint32_t)((sg ^ bxr[g]) << 4);
                uint32_t Bh[4];
                asm volatile("ldmatrix.sync.aligned.m8n8.x4.shared.b16 {%0,%1,%2,%3}, [%4];"
                             : "=r"(Bh[0]), "=r"(Bh[1]), "=r"(Bh[2]), "=r"(Bh[3]) : "r"(ad));
#define MMA_(ACC, AR, B0r, B1r) \
    asm volatile("mma.sync.aligned.m16n8k16.row.col.f32.f16.f16.f32 " \
        "{%0,%1,%2,%3}, {%4,%5,%6,%7}, {%8,%9}, {%0,%1,%2,%3};" \
        : "+f"(ACC[0]), "+f"(ACC[1]), "+f"(ACC[2]), "+f"(ACC[3]) \
        : "r"(AR[0]), "r"(AR[1]), "r"(AR[2]), "r"(AR[3]), "r"(B0r), "r"(B1r))
                #pragma unroll
                for (int f = 0; f < 2; ++f) {
                    MMA_(acc[f][2*g],   Ah[f], Bh[0], Bh[2]);
                    MMA_(acc[f][2*g+1], Ah[f], Bh[1], Bh[3]);
                }
#undef MMA_
            }
        }
        __syncthreads();
        if (c < 2) ISSUE_CHUNK(c + 2, bo);
    }

    // ---- epilogue: scale by c[b,i], store
    const int iw = (n0 >> 6) + wn;                 // this warp's single i
    #pragma unroll
    for (int f = 0; f < 2; ++f) {
        const int br0 = b0 + wm * 32 + f * 16 + (lane >> 2);
        const float cf0 = g_c[br0 * F_ + iw];
        const float cf1 = g_c[(br0 + 8) * F_ + iw];
        float* o0 = out + (size_t)br0 * 16384 + n0 + wn * 64;
        float* o1 = out + (size_t)(br0 + 8) * 16384 + n0 + wn * 64;
        #pragma unroll
        for (int g = 0; g < 4; ++g)
            #pragma unroll
            for (int h8 = 0; h8 < 2; ++h8) {
                const int dn = g * 16 + h8 * 8 + (lane & 3) * 2;
                const float* a4 = acc[f][2*g + h8];
                *(float2*)(o0 + dn) = make_float2(a4[0] * cf0, a4[1] * cf0);
                *(float2*)(o1 + dn) = make_float2(a4[2] * cf1, a4[3] * cf1);
            }
    }
}

// ---------------- launch ------------------------------------------------------
extern "C" void kernel_launch(void* const* d_in, const int* in_sizes, int n_in,
                              void* d_out, int out_size)
{
    const float* feature   = (const float*)d_in[0];
    const float* indicator = (const float*)d_in[1];
    const float* W_qk      = (const float*)d_in[2];
    const float* W_qkv     = (const float*)d_in[3];
    float* out = (float*)d_out;

    cudaFuncSetAttribute(kG, cudaFuncAttributeMaxDynamicSharedMemorySize, SMTOT);

    kA1<<<F_, 320>>>(indicator, W_qk, W_qkv);
    kAB<<<512 + (B_ * F_) / 32, 256>>>(feature);
    kG<<<dim3(64, 16), 256, SMTOT>>>(out);
}